// round 7
// baseline (speedup 1.0000x reference)
#include <cuda_runtime.h>

// Janossy pooling, k=2, n=2048, d=32 — ONE kernel, tiled pair-sum,
// leaderless fire-and-forget epilogue, minimized launch footprint.
//
// out[1][d] = (1/C) sum_{i,j} [j ≺ i] x_i[d],  out[0][d] = (1/C) sum_{i,j} [i ≺ j] x_i[d]
// (j≺i: key_j<key_i, ties by index; exactly one holds per (i,j), i!=j).
// Block (itile,jtile): 256 i-rows x 256 j-keys. Partial count c per row; the
// complement is 256 - c - [i in this j-slice]. Summed over 8 jtiles -> exact.
//
// Replay-safe zeroing: block 0 / warp 0 atomicExch-zeroes out[0:64], fences,
// bumps monotone g_zflag. Every block takes a monotone entry ticket; epoch =
// tick/GRID. Before its final RED.ADD each block acquire-polls
// g_zflag >= epoch+1 (already set by then -> one L2 read), then fire-and-forget.

#define NROWS 2048
#define NDIM  32
#define BLOCK 512                 // 16 warps x 16 rows = 256 rows per block
#define JT    256                 // keys per j-slice
#define GRID  64                  // 8 itiles x 8 jtiles

__device__ unsigned int g_start;  // monotone entry ticket
__device__ unsigned int g_zflag;  // monotone "out zeroed" epoch counter

__global__ __launch_bounds__(BLOCK) void janossy_ff64(const float* __restrict__ X,
                                                      float* __restrict__ out) {
    __shared__ float    skeys[JT];
    __shared__ float    sacc[2 * NDIM];
    __shared__ unsigned s_tick;

    const int tid   = threadIdx.x;
    const int warp  = tid >> 5;
    const int lane  = tid & 31;
    const int itile = blockIdx.x >> 3;     // 0..7 -> 256 rows
    const int jtile = blockIdx.x & 7;      // 0..7 -> 256 keys

    // Block 0 / warp 0: zero out for this replay (overlapped with all work).
    if (blockIdx.x == 0 && warp == 0) {
        atomicExch(&out[lane], 0.0f);
        atomicExch(&out[lane + NDIM], 0.0f);
        __syncwarp();
        __threadfence();                   // release zeros before flag
        if (lane == 0) atomicAdd(&g_zflag, 1u);
    }

    // Entry ticket -> replay epoch (overlapped with staging).
    if (tid == 0) s_tick = atomicAdd(&g_start, 1u);

    // Stage this block's 256-key slice (8 same-jtile blocks share lines).
    if (tid < JT) skeys[tid] = X[(jtile * JT + tid) * NDIM];
    if (tid < 2 * NDIM) sacc[tid] = 0.0f;

    // Preload this warp's 16 rows (coalesced, MLP=16).
    const int rbase = itile * 256 + warp * 16;
    float xr[16];
    #pragma unroll
    for (int t = 0; t < 16; t++) xr[t] = X[(rbase + t) * NDIM + lane];

    __syncthreads();
    const unsigned epoch = s_tick / GRID;

    const float4* sk4 = reinterpret_cast<const float4*>(skeys);
    float acc0 = 0.0f, acc1 = 0.0f;        // lane == feature dim

    #pragma unroll
    for (int t = 0; t < 16; t++) {
        const int   i  = rbase + t;
        const float x  = xr[t];
        const float xi = __shfl_sync(0xffffffffu, x, 0);   // key_i = x_i[0]

        int cnt = 0;
        #pragma unroll
        for (int m = 0; m < 2; m++) {
            const int    q  = lane + m * 32;
            const float4 kv = sk4[q];
            const int    jb = jtile * JT + q * 4;
            cnt += (int)(kv.x < xi) | ((int)(kv.x == xi) & (int)(jb + 0 < i));
            cnt += (int)(kv.y < xi) | ((int)(kv.y == xi) & (int)(jb + 1 < i));
            cnt += (int)(kv.z < xi) | ((int)(kv.z == xi) & (int)(jb + 2 < i));
            cnt += (int)(kv.w < xi) | ((int)(kv.w == xi) & (int)(jb + 3 < i));
        }
        const int c  = __reduce_add_sync(0xffffffffu, cnt);   // partial rank
        const int cp = JT - c - (int)((i >> 8) == jtile);     // i in this slice?

        acc1 += (float)c  * x;
        acc0 += (float)cp * x;
    }

    const float invC = 1.0f / 2096128.0f;
    atomicAdd(&sacc[lane],        acc0 * invC);
    atomicAdd(&sacc[NDIM + lane], acc1 * invC);
    __syncthreads();

    // Epilogue (warp 0): acquire-poll zero flag (expected already set), then
    // fire-and-forget RED.ADD into out.
    if (warp == 0) {
        unsigned v;
        do {
            asm volatile("ld.acquire.gpu.u32 %0, [%1];" : "=r"(v) : "l"(&g_zflag));
        } while (v < epoch + 1u);
        atomicAdd(&out[lane],        sacc[lane]);
        atomicAdd(&out[lane + NDIM], sacc[lane + NDIM]);
    }
}

extern "C" void kernel_launch(void* const* d_in, const int* in_sizes, int n_in,
                              void* d_out, int out_size) {
    const float* X = (const float*)d_in[0];
    janossy_ff64<<<GRID, BLOCK>>>(X, (float*)d_out);
}

// round 8
// speedup vs baseline: 1.1051x; 1.1051x over previous
#include <cuda_runtime.h>

// Janossy pooling, k=2, n=2048, d=32 — ONE kernel, tiled pair-sum,
// 64-bit packed rank comparisons, fire-and-forget epilogue.
//
// out[1][d] = (1/C) sum_{i,j} [j ≺ i] x_i[d],  out[0][d] = (1/C) sum_{i,j} [i ≺ j] x_i[d]
// (≺ : key order, ties by original index == stable argsort).
// Keys packed as k64 = (ord(key) << 16) | index, with ord() the standard
// monotone float->uint32 map (bits ^ ((bits>>31)? 0xFFFFFFFF : 0x80000000)).
// Then  j ≺ i  <=>  k64_j < k64_i  — a single unsigned 64-bit compare.
//
// Block (itile,jtile) of a 16x8 grid: 128 i-rows x 256 j-keys.
// Partial count c per row; complement = 256 - c - [i in this j-slice].
//
// Replay-safe zeroing: block 0 / warp 0 atomicExch-zeroes out[0:64], fences,
// bumps monotone g_zflag. Each block takes a monotone entry ticket
// (epoch = tick/GRID) and acquire-polls g_zflag >= epoch+1 EARLY (before the
// compute loop) so the wait is fully overlapped; program order then puts the
// final RED.ADDs after the acquire.

#define NROWS 2048
#define NDIM  32
#define BLOCK 512                 // 16 warps x 8 rows = 128 rows per block
#define JT    256                 // keys per j-slice
#define GRID  128                 // 16 itiles x 8 jtiles

__device__ unsigned int g_start;  // monotone entry ticket
__device__ unsigned int g_zflag;  // monotone "out zeroed" epoch counter

__device__ __forceinline__ unsigned int ordf(float f) {
    unsigned int b = __float_as_uint(f);
    return b ^ ((((int)b >> 31) | 0x80000000u));
}

__global__ __launch_bounds__(BLOCK) void janossy_p64(const float* __restrict__ X,
                                                     float* __restrict__ out) {
    __shared__ unsigned long long skey[JT];
    __shared__ float              sacc[2 * NDIM];
    __shared__ unsigned           s_tick;

    const int tid   = threadIdx.x;
    const int warp  = tid >> 5;
    const int lane  = tid & 31;
    const int itile = blockIdx.x >> 3;     // 0..15
    const int jtile = blockIdx.x & 7;      // 0..7

    // Block 0 / warp 0: zero out for this replay (overlapped with all work).
    if (blockIdx.x == 0 && warp == 0) {
        atomicExch(&out[lane], 0.0f);
        atomicExch(&out[lane + NDIM], 0.0f);
        __syncwarp();
        __threadfence();                   // release zeros before flag
        if (lane == 0) atomicAdd(&g_zflag, 1u);
    }

    // Entry ticket -> replay epoch (overlapped with staging).
    if (tid == 0) s_tick = atomicAdd(&g_start, 1u);

    // Stage this block's 256-key slice as packed 64-bit sort keys.
    if (tid < JT) {
        const int j = jtile * JT + tid;
        const float k = X[j * NDIM];
        skey[tid] = ((unsigned long long)ordf(k) << 16) | (unsigned)j;
    }
    if (tid < 2 * NDIM) sacc[tid] = 0.0f;

    // Preload this warp's 8 rows (coalesced, MLP=8).
    const int rbase = itile * 128 + warp * 8;
    float xr[8];
    #pragma unroll
    for (int t = 0; t < 8; t++) xr[t] = X[(rbase + t) * NDIM + lane];

    __syncthreads();

    // EARLY acquire-poll: overlap the zero-flag wait with the compute loop.
    if (warp == 0) {
        const unsigned target = s_tick / GRID + 1u;
        unsigned v;
        do {
            asm volatile("ld.acquire.gpu.u32 %0, [%1];" : "=r"(v) : "l"(&g_zflag));
        } while (v < target);
    }

    const ulonglong2* sk2 = reinterpret_cast<const ulonglong2*>(skey);
    float acc0 = 0.0f, acc1 = 0.0f;        // lane == feature dim

    #pragma unroll
    for (int t = 0; t < 8; t++) {
        const int   i  = rbase + t;
        const float x  = xr[t];
        const float xi = __shfl_sync(0xffffffffu, x, 0);   // key_i = x_i[0]
        const unsigned long long my = ((unsigned long long)ordf(xi) << 16) | (unsigned)i;

        int cnt = 0;
        #pragma unroll
        for (int m = 0; m < 4; m++) {                      // 128 ulonglong2
            const ulonglong2 kv = sk2[lane + m * 32];      // LDS.128, conflict-free
            cnt += (int)(kv.x < my);
            cnt += (int)(kv.y < my);
        }
        const int c  = __reduce_add_sync(0xffffffffu, cnt);   // partial rank
        const int cp = JT - c - (int)((i >> 8) == jtile);     // i in this slice?

        acc1 += (float)c  * x;
        acc0 += (float)cp * x;
    }

    const float invC = 1.0f / 2096128.0f;
    atomicAdd(&sacc[lane],        acc0 * invC);
    atomicAdd(&sacc[NDIM + lane], acc1 * invC);
    __syncthreads();

    // Epilogue: fire-and-forget RED.ADD (acquire already satisfied above).
    if (warp == 0) {
        atomicAdd(&out[lane],        sacc[lane]);
        atomicAdd(&out[lane + NDIM], sacc[lane + NDIM]);
    }
}

extern "C" void kernel_launch(void* const* d_in, const int* in_sizes, int n_in,
                              void* d_out, int out_size) {
    const float* X = (const float*)d_in[0];
    janossy_p64<<<GRID, BLOCK>>>(X, (float*)d_out);
}